// round 8
// baseline (speedup 1.0000x reference)
#include <cuda_runtime.h>
#include <cuda_bf16.h>

#define BATCH   32768
#define HID     128
#define INF     784
#define NCLS    10
#define TSTEPS  20

#define DECAYF  0.25f
#define THRESHF 1.0f
#define EPSM    2e-4f

#define KCHUNKS (INF / 16)      // 49
#define FIXCAP  (1 << 21)

// Scratch (device globals)
__device__ float    g_c2[(size_t)TSTEPS * BATCH * NCLS];
__device__ unsigned g_fix_list[FIXCAP];
__device__ unsigned g_fix_cnt;
__device__ __align__(16) unsigned short g_w1a[HID * INF];   // bf16 hi plane
__device__ __align__(16) unsigned short g_w1b[HID * INF];   // bf16 lo plane

// ---------------------------------------------------------------------------
__device__ __forceinline__ void split2(float v, unsigned short& h0, unsigned short& h1)
{
    __nv_bfloat16 b0 = __float2bfloat16_rn(v);
    float r = v - __bfloat162float(b0);
    __nv_bfloat16 b1 = __float2bfloat16_rn(r);
    h0 = __bfloat16_as_ushort(b0);
    h1 = __bfloat16_as_ushort(b1);
}

__device__ __forceinline__ void mma_bf16(float* d, const unsigned* a, const unsigned* b)
{
    asm volatile(
        "mma.sync.aligned.m16n8k16.row.col.f32.bf16.bf16.f32 "
        "{%0,%1,%2,%3}, {%4,%5,%6,%7}, {%8,%9}, {%0,%1,%2,%3};"
        : "+f"(d[0]), "+f"(d[1]), "+f"(d[2]), "+f"(d[3])
        : "r"(a[0]), "r"(a[1]), "r"(a[2]), "r"(a[3]), "r"(b[0]), "r"(b[1]));
}

__global__ void k0_init(const float* __restrict__ W1)
{
    if (blockIdx.x == 0 && threadIdx.x == 0) g_fix_cnt = 0;
    int i = blockIdx.x * blockDim.x + threadIdx.x;
    if (i < HID * INF) {
        unsigned short h0, h1;
        split2(W1[i], h0, h1);
        g_w1a[i] = h0;
        g_w1b[i] = h1;
    }
}

// ---------------------------------------------------------------------------
// K1 fused: GEMM1 (bf16x2-split, 3 MMA products) -> LIF1 -> spikes (gmem)
//           -> GEMM2 exact fmaf chains -> g_c2.
// Tile M=64 x N=128, 256 threads = 8 warps (2m x 4n).
// SMEM: mainloop A/B stages (36.9KB) reused in epilogue as spike tile + W2t.
// ---------------------------------------------------------------------------
#define ASTRIDE 24
#define SPK_STRIDE 130          // floats per spike row (even -> float2 aligned)

__global__ __launch_bounds__(256) void k1_fused(
    const float* __restrict__ x, const float* __restrict__ b1,
    const float* __restrict__ W2, float* __restrict__ out_spk)
{
    __shared__ __align__(16) char SMEMU[41472];
    // mainloop aliases: A planes at 0 (4 x 3072B), B planes at 12288 (4 x 6144B)
    // epilogue aliases: Spk (64 x 130 f32 = 33280B) at 0, W2t (128 x 16 f32) at 33280

    const int tid  = threadIdx.x;
    const int lane = tid & 31;
    const int wid  = tid >> 5;
    const int g    = lane >> 2;
    const int tg   = lane & 3;
    const int wm   = wid >> 2;
    const int wn   = wid & 3;
    const int m0   = blockIdx.x * 64;

    const int sm  = tid >> 2;           // A stage row 0..63
    const int skq = (tid & 3) * 4;      // A stage k 0,4,8,12
    const int bn  = tid >> 1;           // B stage n 0..127
    const int bkh = (tid & 1) * 8;      // B stage k half

    float acc[2][4][4];
    #pragma unroll
    for (int mt = 0; mt < 2; mt++)
        #pragma unroll
        for (int nt = 0; nt < 4; nt++)
            #pragma unroll
            for (int r = 0; r < 4; r++) acc[mt][nt][r] = 0.0f;

    // ---- prologue: stage chunk 0 into buf 0 ----
    {
        unsigned short* A0 = (unsigned short*)SMEMU;                      // buf0 s0
        unsigned short* A1 = (unsigned short*)SMEMU + 64 * ASTRIDE;       // buf0 s1
        unsigned short* B0 = (unsigned short*)(SMEMU + 12288);
        unsigned short* B1 = (unsigned short*)(SMEMU + 12288) + 128 * ASTRIDE;

        float4 ax = *reinterpret_cast<const float4*>(&x[(size_t)(m0 + sm) * INF + skq]);
        float av[4] = {ax.x, ax.y, ax.z, ax.w};
        unsigned short p0[4], p1[4];
        #pragma unroll
        for (int i = 0; i < 4; i++) split2(av[i], p0[i], p1[i]);
        *reinterpret_cast<uint2*>(&A0[sm * ASTRIDE + skq]) = *reinterpret_cast<uint2*>(p0);
        *reinterpret_cast<uint2*>(&A1[sm * ASTRIDE + skq]) = *reinterpret_cast<uint2*>(p1);

        uint4 va = *reinterpret_cast<const uint4*>(&g_w1a[bn * INF + bkh]);
        uint4 vb = *reinterpret_cast<const uint4*>(&g_w1b[bn * INF + bkh]);
        *reinterpret_cast<uint4*>(&B0[bn * ASTRIDE + bkh]) = va;
        *reinterpret_cast<uint4*>(&B1[bn * ASTRIDE + bkh]) = vb;
    }
    __syncthreads();

    int buf = 0;
    for (int kc = 0; kc < KCHUNKS; kc++) {
        // prefetch next chunk
        float4 pax;
        uint4 pba, pbb;
        if (kc < KCHUNKS - 1) {
            int k0 = (kc + 1) * 16;
            pax = *reinterpret_cast<const float4*>(&x[(size_t)(m0 + sm) * INF + k0 + skq]);
            pba = *reinterpret_cast<const uint4*>(&g_w1a[bn * INF + k0 + bkh]);
            pbb = *reinterpret_cast<const uint4*>(&g_w1b[bn * INF + k0 + bkh]);
        }

        // fragments
        unsigned aF[2][2][4];
        #pragma unroll
        for (int s = 0; s < 2; s++)
            #pragma unroll
            for (int mt = 0; mt < 2; mt++) {
                const unsigned short* ap = (unsigned short*)SMEMU
                    + (buf * 2 + s) * (64 * ASTRIDE) + (wm * 32 + mt * 16) * ASTRIDE;
                aF[s][mt][0] = *reinterpret_cast<const unsigned*>(&ap[(g)     * ASTRIDE + tg * 2]);
                aF[s][mt][1] = *reinterpret_cast<const unsigned*>(&ap[(g + 8) * ASTRIDE + tg * 2]);
                aF[s][mt][2] = *reinterpret_cast<const unsigned*>(&ap[(g)     * ASTRIDE + tg * 2 + 8]);
                aF[s][mt][3] = *reinterpret_cast<const unsigned*>(&ap[(g + 8) * ASTRIDE + tg * 2 + 8]);
            }
        unsigned bF[2][4][2];
        #pragma unroll
        for (int s = 0; s < 2; s++)
            #pragma unroll
            for (int nt = 0; nt < 4; nt++) {
                const unsigned short* bp = (unsigned short*)(SMEMU + 12288)
                    + (buf * 2 + s) * (128 * ASTRIDE) + (wn * 32 + nt * 8 + g) * ASTRIDE;
                bF[s][nt][0] = *reinterpret_cast<const unsigned*>(&bp[tg * 2]);
                bF[s][nt][1] = *reinterpret_cast<const unsigned*>(&bp[tg * 2 + 8]);
            }

        // 3 split-products: a0b0, a0b1, a1b0
        #pragma unroll
        for (int p = 0; p < 3; p++) {
            const int PI[3] = {0, 0, 1};
            const int PJ[3] = {0, 1, 0};
            int i = PI[p], j = PJ[p];
            #pragma unroll
            for (int mt = 0; mt < 2; mt++)
                #pragma unroll
                for (int nt = 0; nt < 4; nt++)
                    mma_bf16(acc[mt][nt], aF[i][mt], bF[j][nt]);
        }

        // stage prefetched chunk into other buffer
        if (kc < KCHUNKS - 1) {
            int ob = buf ^ 1;
            unsigned short* A0 = (unsigned short*)SMEMU + (ob * 2 + 0) * (64 * ASTRIDE);
            unsigned short* A1 = (unsigned short*)SMEMU + (ob * 2 + 1) * (64 * ASTRIDE);
            unsigned short* B0 = (unsigned short*)(SMEMU + 12288) + (ob * 2 + 0) * (128 * ASTRIDE);
            unsigned short* B1 = (unsigned short*)(SMEMU + 12288) + (ob * 2 + 1) * (128 * ASTRIDE);
            float av[4] = {pax.x, pax.y, pax.z, pax.w};
            unsigned short p0[4], p1[4];
            #pragma unroll
            for (int i = 0; i < 4; i++) split2(av[i], p0[i], p1[i]);
            *reinterpret_cast<uint2*>(&A0[sm * ASTRIDE + skq]) = *reinterpret_cast<uint2*>(p0);
            *reinterpret_cast<uint2*>(&A1[sm * ASTRIDE + skq]) = *reinterpret_cast<uint2*>(p1);
            *reinterpret_cast<uint4*>(&B0[bn * ASTRIDE + bkh]) = pba;
            *reinterpret_cast<uint4*>(&B1[bn * ASTRIDE + bkh]) = pbb;
        }
        __syncthreads();
        buf ^= 1;
    }

    // ================= epilogue =================
    float cur[2][4][4];
    #pragma unroll
    for (int nt = 0; nt < 4; nt++) {
        float2 bv = *reinterpret_cast<const float2*>(&b1[wn * 32 + nt * 8 + tg * 2]);
        #pragma unroll
        for (int mt = 0; mt < 2; mt++) {
            cur[mt][nt][0] = acc[mt][nt][0] + bv.x;
            cur[mt][nt][1] = acc[mt][nt][1] + bv.y;
            cur[mt][nt][2] = acc[mt][nt][2] + bv.x;
            cur[mt][nt][3] = acc[mt][nt][3] + bv.y;
        }
    }

    float* Spk = (float*)SMEMU;                  // [64][SPK_STRIDE]
    float* W2t = (float*)(SMEMU + 33280);        // [128][16]: o0..4 at +0, o5..9 at +8

    // load W2 transposed (mainloop smem is dead after final sync)
    for (int i = tid; i < HID * NCLS; i += 256) {
        int j = i / NCLS;
        int o = i - j * NCLS;
        W2t[j * 16 + (o < 5 ? o : o + 3)] = W2[o * HID + j];
    }

    float mem[2][4][4];
    unsigned badm[2][4];
    #pragma unroll
    for (int mt = 0; mt < 2; mt++)
        #pragma unroll
        for (int nt = 0; nt < 4; nt++) {
            badm[mt][nt] = 0u;
            #pragma unroll
            for (int r = 0; r < 4; r++) mem[mt][nt][r] = 0.0f;
        }

    const int crow = tid >> 1;       // c2 row (0..63), threads < 128
    const int cog  = tid & 1;        // 0: o0-4, 1: o5-9

    for (int t = 0; t < TSTEPS; t++) {
        float* pt = out_spk + (size_t)t * ((size_t)BATCH * HID);
        #pragma unroll
        for (int mt = 0; mt < 2; mt++) {
            int lr0 = wm * 32 + mt * 16 + g;
            #pragma unroll
            for (int nt = 0; nt < 4; nt++) {
                int n = wn * 32 + nt * 8 + tg * 2;
                float s[4];
                #pragma unroll
                for (int r = 0; r < 4; r++) {
                    float m = fmaf(mem[mt][nt][r], DECAYF, cur[mt][nt][r]);
                    if (fabsf(m - THRESHF) < EPSM) badm[mt][nt] |= (1u << r);
                    s[r] = (m > THRESHF) ? 1.0f : 0.0f;
                    mem[mt][nt][r] = (s[r] != 0.0f) ? 0.0f : m;
                }
                float2 v0 = {s[0], s[1]};
                float2 v1 = {s[2], s[3]};
                *reinterpret_cast<float2*>(&pt[(size_t)(m0 + lr0) * HID + n])     = v0;
                *reinterpret_cast<float2*>(&pt[(size_t)(m0 + lr0 + 8) * HID + n]) = v1;
                *reinterpret_cast<float2*>(&Spk[lr0 * SPK_STRIDE + n])       = v0;
                *reinterpret_cast<float2*>(&Spk[(lr0 + 8) * SPK_STRIDE + n]) = v1;
            }
        }
        __syncthreads();    // spike tile complete

        // c2 for this t: 128 threads, 2 per row, 5 o-chains each (ascending j)
        if (tid < 128) {
            float a0 = 0.f, a1 = 0.f, a2 = 0.f, a3 = 0.f, a4 = 0.f;
            const float* sr = &Spk[crow * SPK_STRIDE];
            #pragma unroll 8
            for (int j = 0; j < HID; j++) {
                float sv = sr[j];
                const float* w = &W2t[j * 16 + cog * 8];
                float4 w4 = *reinterpret_cast<const float4*>(w);
                float  wl = w[4];
                a0 = fmaf(sv, w4.x, a0);
                a1 = fmaf(sv, w4.y, a1);
                a2 = fmaf(sv, w4.z, a2);
                a3 = fmaf(sv, w4.w, a3);
                a4 = fmaf(sv, wl,  a4);
            }
            float* cp = &g_c2[((size_t)t * BATCH + m0 + crow) * NCLS + cog * 5];
            cp[0] = a0; cp[1] = a1; cp[2] = a2; cp[3] = a3; cp[4] = a4;
        }
        __syncthreads();    // Spk reusable next t
    }

    // enqueue risky elements
    #pragma unroll
    for (int mt = 0; mt < 2; mt++)
        #pragma unroll
        for (int nt = 0; nt < 4; nt++)
            if (badm[mt][nt]) {
                #pragma unroll
                for (int r = 0; r < 4; r++)
                    if (badm[mt][nt] & (1u << r)) {
                        int row = m0 + wm * 32 + mt * 16 + g + ((r >> 1) ? 8 : 0);
                        int col = wn * 32 + nt * 8 + tg * 2 + (r & 1);
                        unsigned pos = atomicAdd(&g_fix_cnt, 1u);
                        if (pos < FIXCAP)
                            g_fix_list[pos] = (unsigned)(row * HID + col);
                    }
            }
}

// ---------------------------------------------------------------------------
// K1b fixup: exact sequential-k fp32 recompute of spikes (bitwise R1 recipe).
// ---------------------------------------------------------------------------
__global__ __launch_bounds__(128) void k1_fixup(
    const float* __restrict__ x, const float* __restrict__ W1,
    const float* __restrict__ b1, float* __restrict__ out_spk)
{
    const unsigned cnt = min(*(volatile unsigned*)&g_fix_cnt, (unsigned)FIXCAP);
    const int stride = gridDim.x * blockDim.x;

    for (unsigned i = blockIdx.x * blockDim.x + threadIdx.x; i < cnt; i += stride) {
        unsigned idx = g_fix_list[i];
        int b = idx >> 7;
        int j = idx & (HID - 1);

        const float* xr = x  + (size_t)b * INF;
        const float* wr = W1 + (size_t)j * INF;
        float a = 0.0f;
        for (int k = 0; k < INF; k++)
            a = fmaf(__ldg(&xr[k]), __ldg(&wr[k]), a);
        float curv = a + __ldg(&b1[j]);

        float m = 0.0f;
        for (int t = 0; t < TSTEPS; t++) {
            m = fmaf(m, DECAYF, curv);
            float s = (m > THRESHF) ? 1.0f : 0.0f;
            out_spk[(size_t)t * ((size_t)BATCH * HID) + idx] = s;
            m = (s != 0.0f) ? 0.0f : m;
        }
    }
}

// ---------------------------------------------------------------------------
// K3fix: recompute exact c2 rows (all t) for flagged batch rows from the
// corrected spikes. One thread per (fix entry, t). Duplicates are idempotent.
// ---------------------------------------------------------------------------
__global__ __launch_bounds__(256) void k3_fix(
    const float* __restrict__ spk, const float* __restrict__ W2)
{
    __shared__ float W2t[HID][12];
    const int tid = threadIdx.x;
    for (int i = tid; i < HID * NCLS; i += 256) {
        int j = i / NCLS;
        int o = i - j * NCLS;
        W2t[j][o] = W2[o * HID + j];
    }
    __syncthreads();

    const unsigned cnt = min(*(volatile unsigned*)&g_fix_cnt, (unsigned)FIXCAP);
    const unsigned total = cnt * TSTEPS;
    const unsigned stride = gridDim.x * blockDim.x;

    for (unsigned i = blockIdx.x * blockDim.x + tid; i < total; i += stride) {
        unsigned e = i / TSTEPS;
        int t = i - e * TSTEPS;
        int b = g_fix_list[e] >> 7;

        const float* sr = spk + (size_t)t * ((size_t)BATCH * HID) + (size_t)b * HID;
        float acc[NCLS];
        #pragma unroll
        for (int o = 0; o < NCLS; o++) acc[o] = 0.0f;

        for (int j = 0; j < HID; j++) {
            float s = __ldg(&sr[j]);
            const float* wr = W2t[j];
            float4 w0 = *reinterpret_cast<const float4*>(wr);
            float4 w1 = *reinterpret_cast<const float4*>(wr + 4);
            float2 w2 = *reinterpret_cast<const float2*>(wr + 8);
            acc[0] = fmaf(s, w0.x, acc[0]);
            acc[1] = fmaf(s, w0.y, acc[1]);
            acc[2] = fmaf(s, w0.z, acc[2]);
            acc[3] = fmaf(s, w0.w, acc[3]);
            acc[4] = fmaf(s, w1.x, acc[4]);
            acc[5] = fmaf(s, w1.y, acc[5]);
            acc[6] = fmaf(s, w1.z, acc[6]);
            acc[7] = fmaf(s, w1.w, acc[7]);
            acc[8] = fmaf(s, w2.x, acc[8]);
            acc[9] = fmaf(s, w2.y, acc[9]);
        }
        float* cp = &g_c2[((size_t)t * BATCH + b) * NCLS];
        #pragma unroll
        for (int o = 0; o < NCLS; o++) cp[o] = acc[o];
    }
}

// ---------------------------------------------------------------------------
__global__ __launch_bounds__(256) void k4_lif2(
    const float* __restrict__ b2, float* __restrict__ outp)
{
    const int id = blockIdx.x * blockDim.x + threadIdx.x;
    const int o = id % NCLS;
    const float bias = __ldg(&b2[o]);

    float mem = 0.0f, acc = 0.0f;
    #pragma unroll
    for (int t = 0; t < TSTEPS; t++) {
        float v = fmaf(mem, DECAYF, g_c2[(size_t)t * (BATCH * NCLS) + id]);
        v = v + bias;
        float s = (v > THRESHF) ? 1.0f : 0.0f;
        acc += s;
        mem = (s != 0.0f) ? 0.0f : v;
    }
    outp[id] = acc;
}

// ---------------------------------------------------------------------------
extern "C" void kernel_launch(void* const* d_in, const int* in_sizes, int n_in,
                              void* d_out, int out_size)
{
    const float* x  = (const float*)d_in[0];
    const float* W1 = (const float*)d_in[1];
    const float* b1 = (const float*)d_in[2];
    const float* W2 = (const float*)d_in[3];
    const float* b2 = (const float*)d_in[4];
    float* out = (float*)d_out;

    float* out_output = out;
    float* out_spk    = out + (size_t)BATCH * NCLS;

    k0_init<<<(HID * INF + 255) / 256, 256>>>(W1);
    k1_fused<<<BATCH / 64, 256>>>(x, b1, W2, out_spk);
    k1_fixup<<<256, 128>>>(x, W1, b1, out_spk);
    k3_fix<<<512, 256>>>(out_spk, W2);
    k4_lif2<<<(BATCH * NCLS) / 256, 256>>>(b2, out_output);
}